// round 11
// baseline (speedup 1.0000x reference)
#include <cuda_runtime.h>

#define B_DIM 4
#define T_DIM 1024
#define VD    512
#define HALF  256
#define NL    64
#define C_DIM 256

#define GRID    256
#define THREADS 512

// Phase-B task decomposition: 16-d chunks, 2 per block-iteration (one per
// 256-thread group), 1024 tasks total.
#define DC16    16
#define NTASKB  (NL * (HALF / DC16))    // 1024

// Scratch A[b][l][d] : 256 KB, each cell written exactly once (no zero-init).
__device__ float g_A[B_DIM * NL * HALF];

// Device-wide barrier state (monotonic epoch — survives graph replays).
__device__ unsigned g_bar  = 0;
__device__ unsigned g_base = 0;

__global__ void __launch_bounds__(THREADS, 2)
vb_fused_kernel(const int*   __restrict__ indices,
                const float* __restrict__ scores,
                const int*   __restrict__ label,
                const int*   __restrict__ index_sel,
                const float* __restrict__ weight,
                const float* __restrict__ W,
                float*       __restrict__ out) {
    __shared__ int   s_idx[T_DIM];
    __shared__ float s_sc [T_DIM];
    __shared__ float s_part[256];
    __shared__ float sB[2][B_DIM][DC16];
    __shared__ int   s_cnt;

    const int tid = threadIdx.x;
    const int bid = blockIdx.x;

    // Snapshot barrier base BEFORE any work. All blocks are resident from
    // launch (2 CTAs/SM), so every block snapshots before any block can pass
    // the barrier -> the later g_base update cannot race with this read.
    unsigned base = 0;
    if (tid == 0) base = *((volatile unsigned*)&g_base);

    const int off = (index_sel[0] == 1) ? HALF : 0;

    // =====================================================================
    // Phase A: gather. Block (b,l):
    //   g_A[b,l,d] = sum_{t: label[b,t]=l} scores[b,t] * weight[idx_t, off+d]
    // 512 threads = 2 token-parity groups x 256 d-lanes, 8-way MLP each.
    // =====================================================================
    {
        const int b  = bid / NL;
        const int l  = bid % NL;
        const int tg = tid >> 8;          // token group 0/1
        const int d  = tid & 255;

        // Block 0 zeroes the output (out is 0xAA-poisoned before timing).
        if (bid == 0) {
            out[tid]       = 0.0f;
            out[tid + 512] = 0.0f;
        }
        if (tid == 0) s_cnt = 0;
        __syncthreads();

        #pragma unroll
        for (int j = 0; j < T_DIM / THREADS; j++) {
            int t = b * T_DIM + j * THREADS + tid;
            if (label[t] == l) {
                int pos = atomicAdd(&s_cnt, 1);
                s_idx[pos] = indices[t];
                s_sc [pos] = scores[t];
            }
        }
        __syncthreads();

        const int cnt = s_cnt;
        const int nj  = (cnt - tg + 1) >> 1;       // tokens for this group
        const float* __restrict__ wbase = weight + off + d;

        float acc = 0.0f;
        int k = 0;
        for (; k + 8 <= nj; k += 8) {
            int j0 = tg + 2 * k;
            float v0 = wbase[(long)s_idx[j0 +  0] * VD];
            float v1 = wbase[(long)s_idx[j0 +  2] * VD];
            float v2 = wbase[(long)s_idx[j0 +  4] * VD];
            float v3 = wbase[(long)s_idx[j0 +  6] * VD];
            float v4 = wbase[(long)s_idx[j0 +  8] * VD];
            float v5 = wbase[(long)s_idx[j0 + 10] * VD];
            float v6 = wbase[(long)s_idx[j0 + 12] * VD];
            float v7 = wbase[(long)s_idx[j0 + 14] * VD];
            acc += v0 * s_sc[j0 +  0] + v1 * s_sc[j0 +  2]
                 + v2 * s_sc[j0 +  4] + v3 * s_sc[j0 +  6]
                 + v4 * s_sc[j0 +  8] + v5 * s_sc[j0 + 10]
                 + v6 * s_sc[j0 + 12] + v7 * s_sc[j0 + 14];
        }
        for (; k < nj; k++) {
            int j = tg + 2 * k;
            acc += wbase[(long)s_idx[j] * VD] * s_sc[j];
        }

        if (tg == 1) s_part[d] = acc;
        __syncthreads();
        if (tg == 0)
            g_A[(b * NL + l) * HALF + d] = acc + s_part[d];
    }

    // =====================================================================
    // Device-wide barrier (release g_A writes / acquire before g_A reads).
    // =====================================================================
    __threadfence();
    __syncthreads();
    if (tid == 0) {
        atomicAdd(&g_bar, 1u);
        while (*((volatile unsigned*)&g_bar) - base < GRID) __nanosleep(64);
        if (bid == 0) *((volatile unsigned*)&g_base) = base + GRID;
    }
    __syncthreads();
    __threadfence();

    // =====================================================================
    // Phase B: reduction GEMM. Task (l, dc):
    //   out[b,c] += sum_{d in 16-chunk} g_A[b,l,d] * W[l, off+d, c]
    // 2 groups x 2 iterations = 4 tasks per block; out partials accumulate
    // in registers, single REDG set per thread at the end.
    // =====================================================================
    {
        const int g = tid >> 8;           // c-group 0/1 handles its own task
        const int c = tid & 255;

        float acc0 = 0.f, acc1 = 0.f, acc2 = 0.f, acc3 = 0.f;

        #pragma unroll
        for (int i = 0; i < NTASKB / (GRID * 2); i++) {      // 2 iterations
            const int task = (bid * 2 + g) + i * (GRID * 2); // 0..1023
            const int l    = task >> 4;
            const int d0   = (task & 15) * DC16;

            __syncthreads();
            if (c < B_DIM * DC16) {
                int b  = c / DC16;
                int dd = c % DC16;
                sB[g][b][dd] = g_A[(b * NL + l) * HALF + d0 + dd];
            }
            __syncthreads();

            const float* Wp = W + ((l * VD) + off + d0) * C_DIM + c;
            #pragma unroll
            for (int d = 0; d < DC16; d++) {
                float w = Wp[d * C_DIM];       // coalesced, 16 in flight
                acc0 += sB[g][0][d] * w;
                acc1 += sB[g][1][d] * w;
                acc2 += sB[g][2][d] * w;
                acc3 += sB[g][3][d] * w;
            }
        }

        atomicAdd(&out[0 * C_DIM + c], acc0);
        atomicAdd(&out[1 * C_DIM + c], acc1);
        atomicAdd(&out[2 * C_DIM + c], acc2);
        atomicAdd(&out[3 * C_DIM + c], acc3);
    }
}

// ---------------------------------------------------------------------------
// Launch
// Inputs: indices(i32 B*T), scores(f32 B*T), W(f32 64*512*256),
//   label(i32 B*T), index(i32 scalar), weight(f32 262144*512).
// Output: f32 B*C = 1024.
// ---------------------------------------------------------------------------
extern "C" void kernel_launch(void* const* d_in, const int* in_sizes, int n_in,
                              void* d_out, int out_size) {
    const int*   indices   = (const int*)  d_in[0];
    const float* scores    = (const float*)d_in[1];
    const float* W         = (const float*)d_in[2];
    const int*   label     = (const int*)  d_in[3];
    const int*   index_sel = (const int*)  d_in[4];
    const float* weight    = (const float*)d_in[5];
    float*       out       = (float*)d_out;

    vb_fused_kernel<<<GRID, THREADS>>>(indices, scores, label, index_sel,
                                       weight, W, out);
}

// round 12
// speedup vs baseline: 1.1771x; 1.1771x over previous
#include <cuda_runtime.h>

#define B_DIM 4
#define T_DIM 1024
#define VD    512
#define HALF  256
#define NL    64
#define C_DIM 256

#define SCAT_BLKS 256          // token-parallel scatter blocks (16 tokens each)
#define PREF_BLKS 256          // W L2-prefetch blocks (64 KB each)
#define TOK_PER_BLK (B_DIM * T_DIM / SCAT_BLKS)   // 16

#define DCHUNK 32
#define NCHUNK (HALF / DCHUNK) // 8  -> K2 grid = 512

// Scratch A[b][l][d] : 256 KB. Invariant: ZERO at kernel_launch entry.
//  - static init zeroes it for the first (correctness) call
//  - K2 zero-writes every cell it consumed, restoring the invariant per call
__device__ float g_A[B_DIM * NL * HALF];

// ---------------------------------------------------------------------------
// K1: balanced token scatter + W L2 prefetch + out zeroing.
//   blocks [0,256):   A[b, label[t], d] += scores[t] * weight[indices[t], off+d]
//   blocks [256,512): prefetch.global.L2 over W (16.7 MB -> L2, overlapped)
// ---------------------------------------------------------------------------
__global__ void __launch_bounds__(256)
vb_scatter_kernel(const int*   __restrict__ indices,
                  const float* __restrict__ scores,
                  const int*   __restrict__ label,
                  const int*   __restrict__ index_sel,
                  const float* __restrict__ weight,
                  const float* __restrict__ W,
                  float*       __restrict__ out) {
    const int bid = blockIdx.x;
    const int tid = threadIdx.x;

    if (bid >= SCAT_BLKS) {
        // ---- W prefetch: 64 KB per block, 128B lines, 2 per thread ----
        const char* p = (const char*)W + (size_t)(bid - SCAT_BLKS) * 65536
                      + (size_t)tid * 128;
        asm volatile("prefetch.global.L2 [%0];" :: "l"(p));
        asm volatile("prefetch.global.L2 [%0];" :: "l"(p + 32768));
        return;
    }

    __shared__ int   s_dst[TOK_PER_BLK];   // (b*NL+label)*HALF
    __shared__ int   s_idx[TOK_PER_BLK];
    __shared__ float s_sc [TOK_PER_BLK];

    if (tid < TOK_PER_BLK) {
        int t = bid * TOK_PER_BLK + tid;         // 16 tokens, same batch row
        s_idx[tid] = indices[t];
        s_sc [tid] = scores[t];
        s_dst[tid] = ((bid >> 6) * NL + label[t]) * HALF;
    }
    // Block 0 zeroes out (runs strictly before K2's atomics).
    if (bid == 0) {
        out[tid]       = 0.0f;
        out[tid + 256] = 0.0f;
        out[tid + 512] = 0.0f;
        out[tid + 768] = 0.0f;
    }
    __syncthreads();

    const int off = (index_sel[0] == 1) ? HALF : 0;
    const int d   = tid;
    const float* __restrict__ wbase = weight + off + d;

    // 16 fully independent gather loads in flight, then 16 spread REDGs.
    float v[TOK_PER_BLK];
    #pragma unroll
    for (int j = 0; j < TOK_PER_BLK; j++)
        v[j] = wbase[(long)s_idx[j] * VD];
    #pragma unroll
    for (int j = 0; j < TOK_PER_BLK; j++)
        atomicAdd(&g_A[s_dst[j] + d], v[j] * s_sc[j]);
}

// ---------------------------------------------------------------------------
// K2: reduction GEMM, W served from hot L2.
//   Block (l, dc): out[b,c] += sum_{d in 32-chunk} A[b,l,d] * W[l,off+d,c]
// Reads its exclusive A chunk and writes zeros back (restores invariant).
// ---------------------------------------------------------------------------
__global__ void __launch_bounds__(256)
vb_gemm_kernel(const float* __restrict__ W,
               const int*   __restrict__ index_sel,
               float*       __restrict__ out) {
    const int l  = blockIdx.x / NCHUNK;
    const int d0 = (blockIdx.x % NCHUNK) * DCHUNK;
    const int c  = threadIdx.x;

    const int off = (index_sel[0] == 1) ? HALF : 0;

    __shared__ float sA[B_DIM][DCHUNK];
    if (threadIdx.x < B_DIM * DCHUNK) {
        int b  = threadIdx.x / DCHUNK;
        int dd = threadIdx.x % DCHUNK;
        int a  = (b * NL + l) * HALF + d0 + dd;   // exclusive to this block
        sA[b][dd] = g_A[a];
        g_A[a]    = 0.0f;                         // re-zero for next call
    }
    __syncthreads();

    float acc0 = 0.f, acc1 = 0.f, acc2 = 0.f, acc3 = 0.f;
    const float* Wp = W + ((l * VD) + off + d0) * C_DIM + c;

    #pragma unroll
    for (int d = 0; d < DCHUNK; d++) {
        float w = Wp[d * C_DIM];        // coalesced, L2-hot, 32 in flight
        acc0 += sA[0][d] * w;
        acc1 += sA[1][d] * w;
        acc2 += sA[2][d] * w;
        acc3 += sA[3][d] * w;
    }

    atomicAdd(&out[0 * C_DIM + c], acc0);
    atomicAdd(&out[1 * C_DIM + c], acc1);
    atomicAdd(&out[2 * C_DIM + c], acc2);
    atomicAdd(&out[3 * C_DIM + c], acc3);
}

// ---------------------------------------------------------------------------
// Launch
// Inputs: indices(i32 B*T), scores(f32 B*T), W(f32 64*512*256),
//   label(i32 B*T), index(i32 scalar), weight(f32 262144*512).
// Output: f32 B*C = 1024.
// ---------------------------------------------------------------------------
extern "C" void kernel_launch(void* const* d_in, const int* in_sizes, int n_in,
                              void* d_out, int out_size) {
    const int*   indices   = (const int*)  d_in[0];
    const float* scores    = (const float*)d_in[1];
    const float* W         = (const float*)d_in[2];
    const int*   label     = (const int*)  d_in[3];
    const int*   index_sel = (const int*)  d_in[4];
    const float* weight    = (const float*)d_in[5];
    float*       out       = (float*)d_out;

    vb_scatter_kernel<<<SCAT_BLKS + PREF_BLKS, 256>>>(
        indices, scores, label, index_sel, weight, W, out);
    vb_gemm_kernel<<<NL * NCHUNK, 256>>>(W, index_sel, out);
}